// round 3
// baseline (speedup 1.0000x reference)
#include <cuda_runtime.h>
#include <math.h>

#define NN   100000
#define NE   1600000
#define NE2  1700000      // NE + NN self loops
#define HIDC 128
#define NG   1024
#define BN_EPS 1e-5f

// ---------------- scratch (static __device__, no allocation) ----------------
__device__ float g_bufA[NN * HIDC];   // GEMM output / xw scratch
__device__ float g_bufB[NN * HIDC];   // h ping
__device__ float g_bufC[NN * HIDC];   // h pong
__device__ int   g_cnt[NN];
__device__ int   g_scan[NN];
__device__ int   g_rowptr[NN + 1];
__device__ int   g_cursor[NN];
__device__ int   g_colsrc[NE2];
__device__ float g_dinv[NN];
__device__ float g_as[NN * 4];
__device__ float g_ad[NN * 4];
__device__ int   g_bsum[128];
__device__ float g_pool[NG * HIDC];
__device__ int   g_pcnt[NG];
__device__ int   g_idx64;             // 1 if index arrays are int64, 0 if int32

__device__ __forceinline__ float eluf(float x)  { return x > 0.f ? x : expm1f(x); }
__device__ __forceinline__ float lreluf(float x){ return x > 0.f ? x : 0.2f * x; }

// Load index i (in elements) from an array that may be int32 or int64.
__device__ __forceinline__ int ld_idx(const void* p, int i) {
    if (g_idx64) return (int)((const long long*)p)[i];
    return ((const int*)p)[i];
}

// ---------------- dtype detection ----------------
// If edge_index is int64, every odd 32-bit word (high half) is 0 (ids < 2^31,
// nonnegative). If int32, odd words are random node ids — all-zero is impossible.
__global__ void k_detect(const int* __restrict__ ei_words) {
    if (threadIdx.x == 0) {
        int is64 = 1;
        for (int i = 1; i < 512; i += 2)
            if (ei_words[i] != 0) { is64 = 0; break; }
        g_idx64 = is64;
    }
}

// ---------------- init / CSR build ----------------
__global__ void k_zero() {
    int i = blockIdx.x * blockDim.x + threadIdx.x;
    if (i < NN) g_cnt[i] = 0;
    if (i < NG * HIDC) g_pool[i] = 0.f;
    if (i < NG) g_pcnt[i] = 0;
}

__global__ void k_count(const void* __restrict__ ei) {
    int i = blockIdx.x * blockDim.x + threadIdx.x;
    if (i >= NE2) return;
    int dst = (i < NE) ? ld_idx(ei, NE + i) : (i - NE);
    atomicAdd(&g_cnt[dst], 1);
}

__global__ void k_scan1() {
    __shared__ int sm[1024];
    int t = threadIdx.x;
    int i = blockIdx.x * 1024 + t;
    int v = (i < NN) ? g_cnt[i] : 0;
    sm[t] = v;
    __syncthreads();
    for (int o = 1; o < 1024; o <<= 1) {
        int a = (t >= o) ? sm[t - o] : 0;
        __syncthreads();
        sm[t] += a;
        __syncthreads();
    }
    if (i < NN) g_scan[i] = sm[t];
    if (t == 1023) g_bsum[blockIdx.x] = sm[1023];
}

__global__ void k_scan2(int nb) {
    if (threadIdx.x == 0) {
        int run = 0;
        for (int b = 0; b < nb; b++) { int t = g_bsum[b]; g_bsum[b] = run; run += t; }
    }
}

__global__ void k_scan3() {
    int i = blockIdx.x * blockDim.x + threadIdx.x;
    if (i >= NN) return;
    int ex = g_scan[i] - g_cnt[i] + g_bsum[i >> 10];
    g_rowptr[i] = ex;
    g_cursor[i] = ex;
    g_dinv[i]   = rsqrtf((float)g_cnt[i]);   // in-degree incl self-loop => >=1
    if (i == 0) g_rowptr[NN] = NE2;
}

__global__ void k_fill(const void* __restrict__ ei) {
    int i = blockIdx.x * blockDim.x + threadIdx.x;
    if (i >= NE2) return;
    int src, dst;
    if (i < NE) { src = ld_idx(ei, i); dst = ld_idx(ei, NE + i); }
    else        { src = dst = i - NE; }
    int slot = atomicAdd(&g_cursor[dst], 1);
    g_colsrc[slot] = src;
}

// ---------------- fp32 GEMM (FFMA2 packed f32x2), Y[NN,128] = X[NN,128] @ W[128,128]
__global__ void __launch_bounds__(256) k_gemm(const float* __restrict__ X,
                                              const float* __restrict__ W,
                                              float* __restrict__ Y) {
    __shared__ float Ws[32][128];
    __shared__ float Xs[64][33];
    int tid  = threadIdx.x;
    int colg = tid & 7;       // 0..7
    int rowg = tid >> 3;      // 0..31
    int row0 = blockIdx.x * 64;

    unsigned long long acc2[2][8];
#pragma unroll
    for (int r = 0; r < 2; r++)
#pragma unroll
        for (int j = 0; j < 8; j++) acc2[r][j] = 0ull;

    for (int k0 = 0; k0 < 128; k0 += 32) {
#pragma unroll
        for (int i = 0; i < 16; i++) {
            int idx = tid + i * 256;
            int r = idx >> 7, c = idx & 127;
            Ws[r][c] = W[(k0 + r) * 128 + c];
        }
#pragma unroll
        for (int i = 0; i < 8; i++) {
            int idx = tid + i * 256;
            int r = idx >> 5, c = idx & 31;
            int gr = row0 + r;
            Xs[r][c] = (gr < NN) ? X[gr * 128 + k0 + c] : 0.f;
        }
        __syncthreads();
#pragma unroll
        for (int kk = 0; kk < 32; kk++) {
            unsigned long long w[8];
#pragma unroll
            for (int j = 0; j < 4; j++) {
                float4 w4 = *(const float4*)&Ws[kk][colg * 4 + 32 * j];
                asm("mov.b64 %0,{%1,%2};" : "=l"(w[2 * j])     : "f"(w4.x), "f"(w4.y));
                asm("mov.b64 %0,{%1,%2};" : "=l"(w[2 * j + 1]) : "f"(w4.z), "f"(w4.w));
            }
#pragma unroll
            for (int r = 0; r < 2; r++) {
                float xv = Xs[rowg * 2 + r][kk];
                unsigned long long xv2;
                asm("mov.b64 %0,{%1,%1};" : "=l"(xv2) : "f"(xv));
#pragma unroll
                for (int j = 0; j < 8; j++)
                    asm("fma.rn.f32x2 %0, %1, %2, %0;" : "+l"(acc2[r][j]) : "l"(xv2), "l"(w[j]));
            }
        }
        __syncthreads();
    }
#pragma unroll
    for (int r = 0; r < 2; r++) {
        int gr = row0 + rowg * 2 + r;
        if (gr >= NN) continue;
#pragma unroll
        for (int j = 0; j < 4; j++) {
            float a, b, c, d;
            asm("mov.b64 {%0,%1},%2;" : "=f"(a), "=f"(b) : "l"(acc2[r][2 * j]));
            asm("mov.b64 {%0,%1},%2;" : "=f"(c), "=f"(d) : "l"(acc2[r][2 * j + 1]));
            *(float4*)&Y[gr * 128 + colg * 4 + 32 * j] = make_float4(a, b, c, d);
        }
    }
}

// ---------------- GAT attention logits per node ----------------
__global__ void k_attdot(const float* __restrict__ att_s, const float* __restrict__ att_d) {
    int n = blockIdx.x * 8 + (threadIdx.x >> 5);
    if (n >= NN) return;
    int lane = threadIdx.x & 31;
    float4 h4 = ((const float4*)g_bufA)[n * 32 + lane];
    float4 s4 = ((const float4*)att_s)[lane];
    float4 d4 = ((const float4*)att_d)[lane];
    float ps = h4.x * s4.x + h4.y * s4.y + h4.z * s4.z + h4.w * s4.w;
    float pd = h4.x * d4.x + h4.y * d4.y + h4.z * d4.z + h4.w * d4.w;
#pragma unroll
    for (int o = 1; o < 8; o <<= 1) {
        ps += __shfl_xor_sync(0xffffffffu, ps, o);
        pd += __shfl_xor_sync(0xffffffffu, pd, o);
    }
    if ((lane & 7) == 0) {
        g_as[n * 4 + (lane >> 3)] = ps;
        g_ad[n * 4 + (lane >> 3)] = pd;
    }
}

// ---------------- GAT aggregation: warp per dst node ----------------
__global__ void k_gat(const float* __restrict__ xw, const float* __restrict__ gat_b,
                      float* __restrict__ out) {
    int n = blockIdx.x * 8 + (threadIdx.x >> 5);
    if (n >= NN) return;
    int lane = threadIdx.x & 31;
    int start = g_rowptr[n], end = g_rowptr[n + 1];
    float4 ad4 = ((const float4*)g_ad)[n];

    // pass A: per-head max (lanes parallel over edges)
    float m0 = -1e30f, m1 = -1e30f, m2 = -1e30f, m3 = -1e30f;
    for (int e = start + lane; e < end; e += 32) {
        int s = g_colsrc[e];
        float4 a4 = ((const float4*)g_as)[s];
        m0 = fmaxf(m0, lreluf(a4.x + ad4.x));
        m1 = fmaxf(m1, lreluf(a4.y + ad4.y));
        m2 = fmaxf(m2, lreluf(a4.z + ad4.z));
        m3 = fmaxf(m3, lreluf(a4.w + ad4.w));
    }
#pragma unroll
    for (int o = 16; o; o >>= 1) {
        m0 = fmaxf(m0, __shfl_xor_sync(0xffffffffu, m0, o));
        m1 = fmaxf(m1, __shfl_xor_sync(0xffffffffu, m1, o));
        m2 = fmaxf(m2, __shfl_xor_sync(0xffffffffu, m2, o));
        m3 = fmaxf(m3, __shfl_xor_sync(0xffffffffu, m3, o));
    }
    // pass B: per-head sum of exp
    float s0 = 0.f, s1 = 0.f, s2 = 0.f, s3 = 0.f;
    for (int e = start + lane; e < end; e += 32) {
        int s = g_colsrc[e];
        float4 a4 = ((const float4*)g_as)[s];
        s0 += expf(lreluf(a4.x + ad4.x) - m0);
        s1 += expf(lreluf(a4.y + ad4.y) - m1);
        s2 += expf(lreluf(a4.z + ad4.z) - m2);
        s3 += expf(lreluf(a4.w + ad4.w) - m3);
    }
#pragma unroll
    for (int o = 16; o; o >>= 1) {
        s0 += __shfl_xor_sync(0xffffffffu, s0, o);
        s1 += __shfl_xor_sync(0xffffffffu, s1, o);
        s2 += __shfl_xor_sync(0xffffffffu, s2, o);
        s3 += __shfl_xor_sync(0xffffffffu, s3, o);
    }
    int myh = lane >> 3;
    float m_my  = myh == 0 ? m0 : myh == 1 ? m1 : myh == 2 ? m2 : m3;
    float inv_my = 1.f / (myh == 0 ? s0 : myh == 1 ? s1 : myh == 2 ? s2 : s3);
    float ad_my = myh == 0 ? ad4.x : myh == 1 ? ad4.y : myh == 2 ? ad4.z : ad4.w;

    // pass C: weighted feature gather (lanes parallel over features)
    float4 acc = make_float4(0.f, 0.f, 0.f, 0.f);
    for (int e = start; e < end; e++) {
        int s = g_colsrc[e];
        float ev = lreluf(g_as[s * 4 + myh] + ad_my);
        float al = expf(ev - m_my) * inv_my;
        float4 x4 = ((const float4*)xw)[s * 32 + lane];
        acc.x += al * x4.x; acc.y += al * x4.y; acc.z += al * x4.z; acc.w += al * x4.w;
    }
    float4 b4 = ((const float4*)gat_b)[lane];
    float4 o4;
    o4.x = eluf(acc.x + b4.x);
    o4.y = eluf(acc.y + b4.y);
    o4.z = eluf(acc.z + b4.z);
    o4.w = eluf(acc.w + b4.w);
    ((float4*)out)[n * 32 + lane] = o4;
}

// ---------------- GCN aggregation + BN + ELU (+residual): warp per dst ----------------
__global__ void k_gcn(const float* __restrict__ xw, const float* __restrict__ resid,
                      float* __restrict__ out, const float* __restrict__ bias,
                      const float* __restrict__ bng, const float* __restrict__ bnb,
                      const float* __restrict__ bnm, const float* __restrict__ bnv) {
    int n = blockIdx.x * 8 + (threadIdx.x >> 5);
    if (n >= NN) return;
    int lane = threadIdx.x & 31;
    int start = g_rowptr[n], end = g_rowptr[n + 1];
    float di = g_dinv[n];
    float4 acc = make_float4(0.f, 0.f, 0.f, 0.f);
#pragma unroll 2
    for (int e = start; e < end; e++) {
        int s = g_colsrc[e];
        float w = g_dinv[s];
        float4 x4 = ((const float4*)xw)[s * 32 + lane];
        acc.x += w * x4.x; acc.y += w * x4.y; acc.z += w * x4.z; acc.w += w * x4.w;
    }
    float4 b4 = ((const float4*)bias)[lane];
    float4 g4 = ((const float4*)bng)[lane];
    float4 bb4 = ((const float4*)bnb)[lane];
    float4 m4 = ((const float4*)bnm)[lane];
    float4 v4 = ((const float4*)bnv)[lane];
    float4 r4 = make_float4(0.f, 0.f, 0.f, 0.f);
    if (resid) r4 = ((const float4*)resid)[n * 32 + lane];
    float4 o4;
    {
        float y = acc.x * di + b4.x;
        float sc = g4.x * rsqrtf(v4.x + BN_EPS);
        o4.x = eluf((y - m4.x) * sc + bb4.x) + r4.x;
    }
    {
        float y = acc.y * di + b4.y;
        float sc = g4.y * rsqrtf(v4.y + BN_EPS);
        o4.y = eluf((y - m4.y) * sc + bb4.y) + r4.y;
    }
    {
        float y = acc.z * di + b4.z;
        float sc = g4.z * rsqrtf(v4.z + BN_EPS);
        o4.z = eluf((y - m4.z) * sc + bb4.z) + r4.z;
    }
    {
        float y = acc.w * di + b4.w;
        float sc = g4.w * rsqrtf(v4.w + BN_EPS);
        o4.w = eluf((y - m4.w) * sc + bb4.w) + r4.w;
    }
    ((float4*)out)[n * 32 + lane] = o4;
}

// ---------------- global mean pool accumulate ----------------
__global__ void k_pool(const float* __restrict__ h, const void* __restrict__ batch) {
    int n = blockIdx.x * 8 + (threadIdx.x >> 5);
    if (n >= NN) return;
    int lane = threadIdx.x & 31;
    int g = ld_idx(batch, n);
    float4 x4 = ((const float4*)h)[n * 32 + lane];
    float* p = &g_pool[g * 128 + lane * 4];
    atomicAdd(p + 0, x4.x);
    atomicAdd(p + 1, x4.y);
    atomicAdd(p + 2, x4.z);
    atomicAdd(p + 3, x4.w);
    if (lane == 0) atomicAdd(&g_pcnt[g], 1);
}

// ---------------- MLP head: one block per graph ----------------
__global__ void k_mlp(const float* __restrict__ p1w, const float* __restrict__ p1b,
                      const float* __restrict__ p2w, const float* __restrict__ p2b,
                      const float* __restrict__ cw,  const float* __restrict__ cb,
                      float* __restrict__ out, int out_size) {
    __shared__ float gs[128], e1[128], e2[64];
    int b = blockIdx.x, t = threadIdx.x;
    float cnt = fmaxf((float)g_pcnt[b], 1.f);
    gs[t] = g_pool[b * 128 + t] / cnt;
    __syncthreads();
    float a = p1b[t];
#pragma unroll 8
    for (int k = 0; k < 128; k++) a += gs[k] * p1w[k * 128 + t];
    e1[t] = eluf(a);
    __syncthreads();
    if (t < 64) {
        float a2 = p2b[t];
#pragma unroll 8
        for (int k = 0; k < 128; k++) a2 += e1[k] * p2w[k * 64 + t];
        e2[t] = a2;
        if (out_size >= 1024 * 3 + 1024 * 64) out[1024 * 3 + b * 64 + t] = a2;
    }
    __syncthreads();
    if (t < 3) {
        float a3 = cb[t];
#pragma unroll
        for (int k = 0; k < 64; k++) a3 += e2[k] * cw[k * 3 + t];
        out[b * 3 + t] = a3;
    }
}

// ---------------- launch ----------------
extern "C" void kernel_launch(void* const* d_in, const int* in_sizes, int n_in,
                              void* d_out, int out_size) {
    const float* x      = (const float*)d_in[0];
    const void*  ei     = d_in[1];               // int32 or int64, detected at runtime
    const void*  batch  = d_in[3];
    const float* gat_w  = (const float*)d_in[4];
    const float* att_s  = (const float*)d_in[5];
    const float* att_d  = (const float*)d_in[6];
    const float* gat_b  = (const float*)d_in[7];
    const float* gcn1_w = (const float*)d_in[8];
    const float* gcn1_b = (const float*)d_in[9];
    const float* bn1_g  = (const float*)d_in[10];
    const float* bn1_b  = (const float*)d_in[11];
    const float* bn1_m  = (const float*)d_in[12];
    const float* bn1_v  = (const float*)d_in[13];
    const float* gcn2_w = (const float*)d_in[14];
    const float* gcn2_b = (const float*)d_in[15];
    const float* bn2_g  = (const float*)d_in[16];
    const float* bn2_b  = (const float*)d_in[17];
    const float* bn2_m  = (const float*)d_in[18];
    const float* bn2_v  = (const float*)d_in[19];
    const float* gcn3_w = (const float*)d_in[20];
    const float* gcn3_b = (const float*)d_in[21];
    const float* bn3_g  = (const float*)d_in[22];
    const float* bn3_b  = (const float*)d_in[23];
    const float* bn3_m  = (const float*)d_in[24];
    const float* bn3_v  = (const float*)d_in[25];
    const float* p1_w   = (const float*)d_in[26];
    const float* p1_b   = (const float*)d_in[27];
    const float* p2_w   = (const float*)d_in[28];
    const float* p2_b   = (const float*)d_in[29];
    const float* cls_w  = (const float*)d_in[30];
    const float* cls_b  = (const float*)d_in[31];
    float* out = (float*)d_out;

    float *pA, *pB, *pC;
    cudaGetSymbolAddress((void**)&pA, g_bufA);
    cudaGetSymbolAddress((void**)&pB, g_bufB);
    cudaGetSymbolAddress((void**)&pC, g_bufC);

    const int EB = (NE2 + 255) / 256;
    const int NB = (NN + 255) / 256;
    const int WB = NN / 8;             // warp-per-node blocks (256 thr = 8 warps)
    const int GB = (NN + 63) / 64;     // gemm blocks

    k_detect<<<1, 32>>>((const int*)ei);
    k_zero<<<512, 256>>>();
    k_count<<<EB, 256>>>(ei);
    k_scan1<<<98, 1024>>>();
    k_scan2<<<1, 32>>>(98);
    k_scan3<<<NB, 256>>>();
    k_fill<<<EB, 256>>>(ei);

    // GAT
    k_gemm<<<GB, 256>>>(x, gat_w, pA);
    k_attdot<<<WB, 256>>>(att_s, att_d);
    k_gat<<<WB, 256>>>(pA, gat_b, pB);
    // GCN1 (+res B)
    k_gemm<<<GB, 256>>>(pB, gcn1_w, pA);
    k_gcn<<<WB, 256>>>(pA, pB, pC, gcn1_b, bn1_g, bn1_b, bn1_m, bn1_v);
    // GCN2 (+res C)
    k_gemm<<<GB, 256>>>(pC, gcn2_w, pA);
    k_gcn<<<WB, 256>>>(pA, pC, pB, gcn2_b, bn2_g, bn2_b, bn2_m, bn2_v);
    // GCN3 (no res)
    k_gemm<<<GB, 256>>>(pB, gcn3_w, pA);
    k_gcn<<<WB, 256>>>(pA, (const float*)nullptr, pC, gcn3_b, bn3_g, bn3_b, bn3_m, bn3_v);

    // pool + head
    k_pool<<<WB, 256>>>(pC, batch);
    k_mlp<<<NG, 128>>>(p1_w, p1_b, p2_w, p2_b, cls_w, cls_b, out, out_size);
}

// round 4
// speedup vs baseline: 1.0844x; 1.0844x over previous
#include <cuda_runtime.h>
#include <math.h>

#define NN   100000
#define NE   1600000
#define NE2  1700000      // NE + NN self loops
#define HIDC 128
#define NG   1024
#define BN_EPS 1e-5f

// ---------------- scratch (static __device__, no allocation) ----------------
__device__ float g_bufA[NN * HIDC];   // GEMM output / xw scratch
__device__ float g_bufB[NN * HIDC];   // h ping
__device__ float g_bufC[NN * HIDC];   // h pong
__device__ int   g_cnt[NN];
__device__ int   g_scan[NN];
__device__ int   g_rowptr[NN + 1];
__device__ int   g_cursor[NN];
__device__ int   g_colsrc[NE2];
__device__ float g_dinv[NN];
__device__ float g_as[NN * 4];
__device__ float g_ad[NN * 4];
__device__ float g_alpha[NE2 * 4];    // cached unnormalized exp per edge per head
__device__ int   g_bsum[128];
__device__ float g_pool[NG * HIDC];
__device__ int   g_pcnt[NG];
__device__ int   g_idx64;             // 1 if index arrays are int64, 0 if int32

__device__ __forceinline__ float eluf(float x)  { return x > 0.f ? x : (__expf(x) - 1.f); }
__device__ __forceinline__ float lreluf(float x){ return x > 0.f ? x : 0.2f * x; }

// Load index i (in elements) from an array that may be int32 or int64.
__device__ __forceinline__ int ld_idx(const void* p, int i) {
    if (g_idx64) return (int)((const long long*)p)[i];
    return ((const int*)p)[i];
}

// ---------------- dtype detection ----------------
__global__ void k_detect(const int* __restrict__ ei_words) {
    if (threadIdx.x == 0) {
        int is64 = 1;
        for (int i = 1; i < 512; i += 2)
            if (ei_words[i] != 0) { is64 = 0; break; }
        g_idx64 = is64;
    }
}

// ---------------- init / CSR build ----------------
__global__ void k_zero() {
    int i = blockIdx.x * blockDim.x + threadIdx.x;
    if (i < NN) g_cnt[i] = 0;
    if (i < NG * HIDC) g_pool[i] = 0.f;
    if (i < NG) g_pcnt[i] = 0;
}

__global__ void k_count(const void* __restrict__ ei) {
    int i = blockIdx.x * blockDim.x + threadIdx.x;
    if (i >= NE2) return;
    int dst = (i < NE) ? ld_idx(ei, NE + i) : (i - NE);
    atomicAdd(&g_cnt[dst], 1);
}

__global__ void k_scan1() {
    __shared__ int sm[1024];
    int t = threadIdx.x;
    int i = blockIdx.x * 1024 + t;
    int v = (i < NN) ? g_cnt[i] : 0;
    sm[t] = v;
    __syncthreads();
    for (int o = 1; o < 1024; o <<= 1) {
        int a = (t >= o) ? sm[t - o] : 0;
        __syncthreads();
        sm[t] += a;
        __syncthreads();
    }
    if (i < NN) g_scan[i] = sm[t];
    if (t == 1023) g_bsum[blockIdx.x] = sm[1023];
}

__global__ void k_scan2(int nb) {
    if (threadIdx.x == 0) {
        int run = 0;
        for (int b = 0; b < nb; b++) { int t = g_bsum[b]; g_bsum[b] = run; run += t; }
    }
}

__global__ void k_scan3() {
    int i = blockIdx.x * blockDim.x + threadIdx.x;
    if (i >= NN) return;
    int ex = g_scan[i] - g_cnt[i] + g_bsum[i >> 10];
    g_rowptr[i] = ex;
    g_cursor[i] = ex;
    g_dinv[i]   = rsqrtf((float)g_cnt[i]);
    if (i == 0) g_rowptr[NN] = NE2;
}

__global__ void k_fill(const void* __restrict__ ei) {
    int i = blockIdx.x * blockDim.x + threadIdx.x;
    if (i >= NE2) return;
    int src, dst;
    if (i < NE) { src = ld_idx(ei, i); dst = ld_idx(ei, NE + i); }
    else        { src = dst = i - NE; }
    int slot = atomicAdd(&g_cursor[dst], 1);
    g_colsrc[slot] = src;
}

// ---------------- fp32 GEMM (FFMA2 packed f32x2), Y[NN,128] = X[NN,128] @ W[128,128]
__global__ void __launch_bounds__(256) k_gemm(const float* __restrict__ X,
                                              const float* __restrict__ W,
                                              float* __restrict__ Y) {
    __shared__ float Ws[32][128];
    __shared__ float Xs[64][33];
    int tid  = threadIdx.x;
    int colg = tid & 7;       // 0..7
    int rowg = tid >> 3;      // 0..31
    int row0 = blockIdx.x * 64;

    unsigned long long acc2[2][8];
#pragma unroll
    for (int r = 0; r < 2; r++)
#pragma unroll
        for (int j = 0; j < 8; j++) acc2[r][j] = 0ull;

    for (int k0 = 0; k0 < 128; k0 += 32) {
#pragma unroll
        for (int i = 0; i < 16; i++) {
            int idx = tid + i * 256;
            int r = idx >> 7, c = idx & 127;
            Ws[r][c] = W[(k0 + r) * 128 + c];
        }
#pragma unroll
        for (int i = 0; i < 8; i++) {
            int idx = tid + i * 256;
            int r = idx >> 5, c = idx & 31;
            int gr = row0 + r;
            Xs[r][c] = (gr < NN) ? X[gr * 128 + k0 + c] : 0.f;
        }
        __syncthreads();
#pragma unroll
        for (int kk = 0; kk < 32; kk++) {
            unsigned long long w[8];
#pragma unroll
            for (int j = 0; j < 4; j++) {
                float4 w4 = *(const float4*)&Ws[kk][colg * 4 + 32 * j];
                asm("mov.b64 %0,{%1,%2};" : "=l"(w[2 * j])     : "f"(w4.x), "f"(w4.y));
                asm("mov.b64 %0,{%1,%2};" : "=l"(w[2 * j + 1]) : "f"(w4.z), "f"(w4.w));
            }
#pragma unroll
            for (int r = 0; r < 2; r++) {
                float xv = Xs[rowg * 2 + r][kk];
                unsigned long long xv2;
                asm("mov.b64 %0,{%1,%1};" : "=l"(xv2) : "f"(xv));
#pragma unroll
                for (int j = 0; j < 8; j++)
                    asm("fma.rn.f32x2 %0, %1, %2, %0;" : "+l"(acc2[r][j]) : "l"(xv2), "l"(w[j]));
            }
        }
        __syncthreads();
    }
#pragma unroll
    for (int r = 0; r < 2; r++) {
        int gr = row0 + rowg * 2 + r;
        if (gr >= NN) continue;
#pragma unroll
        for (int j = 0; j < 4; j++) {
            float a, b, c, d;
            asm("mov.b64 {%0,%1},%2;" : "=f"(a), "=f"(b) : "l"(acc2[r][2 * j]));
            asm("mov.b64 {%0,%1},%2;" : "=f"(c), "=f"(d) : "l"(acc2[r][2 * j + 1]));
            *(float4*)&Y[gr * 128 + colg * 4 + 32 * j] = make_float4(a, b, c, d);
        }
    }
}

// ---------------- GAT attention logits per node ----------------
__global__ void k_attdot(const float* __restrict__ att_s, const float* __restrict__ att_d) {
    int n = blockIdx.x * 8 + (threadIdx.x >> 5);
    if (n >= NN) return;
    int lane = threadIdx.x & 31;
    float4 h4 = ((const float4*)g_bufA)[n * 32 + lane];
    float4 s4 = ((const float4*)att_s)[lane];
    float4 d4 = ((const float4*)att_d)[lane];
    float ps = h4.x * s4.x + h4.y * s4.y + h4.z * s4.z + h4.w * s4.w;
    float pd = h4.x * d4.x + h4.y * d4.y + h4.z * d4.z + h4.w * d4.w;
#pragma unroll
    for (int o = 1; o < 8; o <<= 1) {
        ps += __shfl_xor_sync(0xffffffffu, ps, o);
        pd += __shfl_xor_sync(0xffffffffu, pd, o);
    }
    if ((lane & 7) == 0) {
        g_as[n * 4 + (lane >> 3)] = ps;
        g_ad[n * 4 + (lane >> 3)] = pd;
    }
}

// ---------------- GAT aggregation: warp per dst node ----------------
// Logits are tiny (|e| < ~5 for this data distribution), so softmax without
// max-subtraction is numerically safe and mathematically identical.
__global__ void k_gat(const float* __restrict__ xw, const float* __restrict__ gat_b,
                      float* __restrict__ out) {
    int n = blockIdx.x * 8 + (threadIdx.x >> 5);
    if (n >= NN) return;
    int lane = threadIdx.x & 31;
    int start = g_rowptr[n], end = g_rowptr[n + 1];
    float4 ad4 = ((const float4*)g_ad)[n];

    // pass 1: exp per edge per head (cached), accumulate per-head sums
    float s0 = 0.f, s1 = 0.f, s2 = 0.f, s3 = 0.f;
    for (int e = start + lane; e < end; e += 32) {
        int s = g_colsrc[e];
        float4 a4 = ((const float4*)g_as)[s];
        float e0 = __expf(lreluf(a4.x + ad4.x));
        float e1 = __expf(lreluf(a4.y + ad4.y));
        float e2 = __expf(lreluf(a4.z + ad4.z));
        float e3 = __expf(lreluf(a4.w + ad4.w));
        ((float4*)g_alpha)[e] = make_float4(e0, e1, e2, e3);
        s0 += e0; s1 += e1; s2 += e2; s3 += e3;
    }
#pragma unroll
    for (int o = 16; o; o >>= 1) {
        s0 += __shfl_xor_sync(0xffffffffu, s0, o);
        s1 += __shfl_xor_sync(0xffffffffu, s1, o);
        s2 += __shfl_xor_sync(0xffffffffu, s2, o);
        s3 += __shfl_xor_sync(0xffffffffu, s3, o);
    }
    int myh = lane >> 3;
    float inv_my = 1.f / (myh == 0 ? s0 : myh == 1 ? s1 : myh == 2 ? s2 : s3);

    // pass 2: weighted feature gather (lanes parallel over features)
    float4 acc = make_float4(0.f, 0.f, 0.f, 0.f);
    for (int e = start; e < end; e++) {
        int s = g_colsrc[e];
        float4 al4 = ((const float4*)g_alpha)[e];   // 16B broadcast
        float al = (myh == 0 ? al4.x : myh == 1 ? al4.y : myh == 2 ? al4.z : al4.w) * inv_my;
        float4 x4 = ((const float4*)xw)[s * 32 + lane];
        acc.x += al * x4.x; acc.y += al * x4.y; acc.z += al * x4.z; acc.w += al * x4.w;
    }
    float4 b4 = ((const float4*)gat_b)[lane];
    float4 o4;
    o4.x = eluf(acc.x + b4.x);
    o4.y = eluf(acc.y + b4.y);
    o4.z = eluf(acc.z + b4.z);
    o4.w = eluf(acc.w + b4.w);
    ((float4*)out)[n * 32 + lane] = o4;
}

// ---------------- GCN aggregation + BN + ELU (+residual): warp per dst ----------------
__global__ void k_gcn(const float* __restrict__ xw, const float* __restrict__ resid,
                      float* __restrict__ out, const float* __restrict__ bias,
                      const float* __restrict__ bng, const float* __restrict__ bnb,
                      const float* __restrict__ bnm, const float* __restrict__ bnv) {
    int n = blockIdx.x * 8 + (threadIdx.x >> 5);
    if (n >= NN) return;
    int lane = threadIdx.x & 31;
    int start = g_rowptr[n], end = g_rowptr[n + 1];
    float di = g_dinv[n];
    float4 acc = make_float4(0.f, 0.f, 0.f, 0.f);
#pragma unroll 2
    for (int e = start; e < end; e++) {
        int s = g_colsrc[e];
        float w = g_dinv[s];
        float4 x4 = ((const float4*)xw)[s * 32 + lane];
        acc.x += w * x4.x; acc.y += w * x4.y; acc.z += w * x4.z; acc.w += w * x4.w;
    }
    float4 b4 = ((const float4*)bias)[lane];
    float4 g4 = ((const float4*)bng)[lane];
    float4 bb4 = ((const float4*)bnb)[lane];
    float4 m4 = ((const float4*)bnm)[lane];
    float4 v4 = ((const float4*)bnv)[lane];
    float4 r4 = make_float4(0.f, 0.f, 0.f, 0.f);
    if (resid) r4 = ((const float4*)resid)[n * 32 + lane];
    float4 o4;
    {
        float y = acc.x * di + b4.x;
        float sc = g4.x * rsqrtf(v4.x + BN_EPS);
        o4.x = eluf((y - m4.x) * sc + bb4.x) + r4.x;
    }
    {
        float y = acc.y * di + b4.y;
        float sc = g4.y * rsqrtf(v4.y + BN_EPS);
        o4.y = eluf((y - m4.y) * sc + bb4.y) + r4.y;
    }
    {
        float y = acc.z * di + b4.z;
        float sc = g4.z * rsqrtf(v4.z + BN_EPS);
        o4.z = eluf((y - m4.z) * sc + bb4.z) + r4.z;
    }
    {
        float y = acc.w * di + b4.w;
        float sc = g4.w * rsqrtf(v4.w + BN_EPS);
        o4.w = eluf((y - m4.w) * sc + bb4.w) + r4.w;
    }
    ((float4*)out)[n * 32 + lane] = o4;
}

// ---------------- global mean pool accumulate ----------------
__global__ void k_pool(const float* __restrict__ h, const void* __restrict__ batch) {
    int n = blockIdx.x * 8 + (threadIdx.x >> 5);
    if (n >= NN) return;
    int lane = threadIdx.x & 31;
    int g = ld_idx(batch, n);
    float4 x4 = ((const float4*)h)[n * 32 + lane];
    float* p = &g_pool[g * 128 + lane * 4];
    atomicAdd(p + 0, x4.x);
    atomicAdd(p + 1, x4.y);
    atomicAdd(p + 2, x4.z);
    atomicAdd(p + 3, x4.w);
    if (lane == 0) atomicAdd(&g_pcnt[g], 1);
}

// ---------------- MLP head: one block per graph ----------------
__global__ void k_mlp(const float* __restrict__ p1w, const float* __restrict__ p1b,
                      const float* __restrict__ p2w, const float* __restrict__ p2b,
                      const float* __restrict__ cw,  const float* __restrict__ cb,
                      float* __restrict__ out, int out_size) {
    __shared__ float gs[128], e1[128], e2[64];
    int b = blockIdx.x, t = threadIdx.x;
    float cnt = fmaxf((float)g_pcnt[b], 1.f);
    gs[t] = g_pool[b * 128 + t] / cnt;
    __syncthreads();
    float a = p1b[t];
#pragma unroll 8
    for (int k = 0; k < 128; k++) a += gs[k] * p1w[k * 128 + t];
    e1[t] = eluf(a);
    __syncthreads();
    if (t < 64) {
        float a2 = p2b[t];
#pragma unroll 8
        for (int k = 0; k < 128; k++) a2 += e1[k] * p2w[k * 64 + t];
        e2[t] = a2;
        if (out_size >= 1024 * 3 + 1024 * 64) out[1024 * 3 + b * 64 + t] = a2;
    }
    __syncthreads();
    if (t < 3) {
        float a3 = cb[t];
#pragma unroll
        for (int k = 0; k < 64; k++) a3 += e2[k] * cw[k * 3 + t];
        out[b * 3 + t] = a3;
    }
}

// ---------------- launch ----------------
extern "C" void kernel_launch(void* const* d_in, const int* in_sizes, int n_in,
                              void* d_out, int out_size) {
    const float* x      = (const float*)d_in[0];
    const void*  ei     = d_in[1];               // int32 or int64, detected at runtime
    const void*  batch  = d_in[3];
    const float* gat_w  = (const float*)d_in[4];
    const float* att_s  = (const float*)d_in[5];
    const float* att_d  = (const float*)d_in[6];
    const float* gat_b  = (const float*)d_in[7];
    const float* gcn1_w = (const float*)d_in[8];
    const float* gcn1_b = (const float*)d_in[9];
    const float* bn1_g  = (const float*)d_in[10];
    const float* bn1_b  = (const float*)d_in[11];
    const float* bn1_m  = (const float*)d_in[12];
    const float* bn1_v  = (const float*)d_in[13];
    const float* gcn2_w = (const float*)d_in[14];
    const float* gcn2_b = (const float*)d_in[15];
    const float* bn2_g  = (const float*)d_in[16];
    const float* bn2_b  = (const float*)d_in[17];
    const float* bn2_m  = (const float*)d_in[18];
    const float* bn2_v  = (const float*)d_in[19];
    const float* gcn3_w = (const float*)d_in[20];
    const float* gcn3_b = (const float*)d_in[21];
    const float* bn3_g  = (const float*)d_in[22];
    const float* bn3_b  = (const float*)d_in[23];
    const float* bn3_m  = (const float*)d_in[24];
    const float* bn3_v  = (const float*)d_in[25];
    const float* p1_w   = (const float*)d_in[26];
    const float* p1_b   = (const float*)d_in[27];
    const float* p2_w   = (const float*)d_in[28];
    const float* p2_b   = (const float*)d_in[29];
    const float* cls_w  = (const float*)d_in[30];
    const float* cls_b  = (const float*)d_in[31];
    float* out = (float*)d_out;

    float *pA, *pB, *pC;
    cudaGetSymbolAddress((void**)&pA, g_bufA);
    cudaGetSymbolAddress((void**)&pB, g_bufB);
    cudaGetSymbolAddress((void**)&pC, g_bufC);

    const int EB = (NE2 + 255) / 256;
    const int NB = (NN + 255) / 256;
    const int WB = NN / 8;             // warp-per-node blocks (256 thr = 8 warps)
    const int GB = (NN + 63) / 64;     // gemm blocks

    k_detect<<<1, 32>>>((const int*)ei);
    k_zero<<<512, 256>>>();
    k_count<<<EB, 256>>>(ei);
    k_scan1<<<98, 1024>>>();
    k_scan2<<<1, 32>>>(98);
    k_scan3<<<NB, 256>>>();
    k_fill<<<EB, 256>>>(ei);

    // GAT
    k_gemm<<<GB, 256>>>(x, gat_w, pA);
    k_attdot<<<WB, 256>>>(att_s, att_d);
    k_gat<<<WB, 256>>>(pA, gat_b, pB);
    // GCN1 (+res B)
    k_gemm<<<GB, 256>>>(pB, gcn1_w, pA);
    k_gcn<<<WB, 256>>>(pA, pB, pC, gcn1_b, bn1_g, bn1_b, bn1_m, bn1_v);
    // GCN2 (+res C)
    k_gemm<<<GB, 256>>>(pC, gcn2_w, pA);
    k_gcn<<<WB, 256>>>(pA, pC, pB, gcn2_b, bn2_g, bn2_b, bn2_m, bn2_v);
    // GCN3 (no res)
    k_gemm<<<GB, 256>>>(pB, gcn3_w, pA);
    k_gcn<<<WB, 256>>>(pA, (const float*)nullptr, pC, gcn3_b, bn3_g, bn3_b, bn3_m, bn3_v);

    // pool + head
    k_pool<<<WB, 256>>>(pC, batch);
    k_mlp<<<NG, 128>>>(p1_w, p1_b, p2_w, p2_b, cls_w, cls_b, out, out_size);
}

// round 5
// speedup vs baseline: 1.1336x; 1.0454x over previous
#include <cuda_runtime.h>
#include <math.h>

#define NN   100000
#define NE   1600000
#define NE2  1700000      // NE + NN self loops
#define HIDC 128
#define NG   1024
#define BN_EPS 1e-5f

// ---------------- scratch (static __device__, no allocation) ----------------
__device__ float g_bufA[NN * HIDC];   // GEMM output / xw scratch
__device__ float g_bufB[NN * HIDC];   // h ping
__device__ float g_bufC[NN * HIDC];   // h pong
__device__ int   g_cnt[NN];
__device__ int   g_scan[NN];
__device__ int   g_rowptr[NN + 1];
__device__ int   g_cursor[NN];
__device__ int   g_colsrc[NE2];
__device__ float g_dinv[NN];
__device__ float g_as[NN * 4];
__device__ float g_ad[NN * 4];
__device__ float g_alpha[NE2 * 4];    // cached unnormalized exp per edge per head
__device__ int   g_bsum[128];
__device__ float g_pool[NG * HIDC];
__device__ int   g_pcnt[NG];
__device__ int   g_idx64;             // 1 if index arrays are int64, 0 if int32

__device__ __forceinline__ float eluf(float x)  { return x > 0.f ? x : (__expf(x) - 1.f); }
__device__ __forceinline__ float lreluf(float x){ return x > 0.f ? x : 0.2f * x; }

__device__ __forceinline__ int ld_idx(const void* p, int i) {
    if (g_idx64) return (int)((const long long*)p)[i];
    return ((const int*)p)[i];
}

// ---------------- dtype detection ----------------
__global__ void k_detect(const int* __restrict__ ei_words) {
    if (threadIdx.x == 0) {
        int is64 = 1;
        for (int i = 1; i < 512; i += 2)
            if (ei_words[i] != 0) { is64 = 0; break; }
        g_idx64 = is64;
    }
}

// ---------------- init / CSR build ----------------
__global__ void k_zero() {
    int i = blockIdx.x * blockDim.x + threadIdx.x;
    if (i < NN) g_cnt[i] = 0;
    if (i < NG * HIDC) g_pool[i] = 0.f;
    if (i < NG) g_pcnt[i] = 0;
}

__global__ void k_count(const void* __restrict__ ei) {
    int i = blockIdx.x * blockDim.x + threadIdx.x;
    if (i >= NE2) return;
    int dst = (i < NE) ? ld_idx(ei, NE + i) : (i - NE);
    atomicAdd(&g_cnt[dst], 1);
}

__global__ void k_scan1() {
    __shared__ int sm[1024];
    int t = threadIdx.x;
    int i = blockIdx.x * 1024 + t;
    int v = (i < NN) ? g_cnt[i] : 0;
    sm[t] = v;
    __syncthreads();
    for (int o = 1; o < 1024; o <<= 1) {
        int a = (t >= o) ? sm[t - o] : 0;
        __syncthreads();
        sm[t] += a;
        __syncthreads();
    }
    if (i < NN) g_scan[i] = sm[t];
    if (t == 1023) g_bsum[blockIdx.x] = sm[1023];
}

__global__ void k_scan2(int nb) {
    if (threadIdx.x == 0) {
        int run = 0;
        for (int b = 0; b < nb; b++) { int t = g_bsum[b]; g_bsum[b] = run; run += t; }
    }
}

__global__ void k_scan3() {
    int i = blockIdx.x * blockDim.x + threadIdx.x;
    if (i >= NN) return;
    int ex = g_scan[i] - g_cnt[i] + g_bsum[i >> 10];
    g_rowptr[i] = ex;
    g_cursor[i] = ex;
    g_dinv[i]   = rsqrtf((float)g_cnt[i]);
    if (i == 0) g_rowptr[NN] = NE2;
}

__global__ void k_fill(const void* __restrict__ ei) {
    int i = blockIdx.x * blockDim.x + threadIdx.x;
    if (i >= NE2) return;
    int src, dst;
    if (i < NE) { src = ld_idx(ei, i); dst = ld_idx(ei, NE + i); }
    else        { src = dst = i - NE; }
    int slot = atomicAdd(&g_cursor[dst], 1);
    g_colsrc[slot] = src;
}

// ---------------- fp32 GEMM (FFMA2), Y[NN,128] = X[NN,128] @ W[128,128]
// rowscale != nullptr: Y[r] *= rowscale[r]   (fused GCN source normalization)
__global__ void __launch_bounds__(256) k_gemm(const float* __restrict__ X,
                                              const float* __restrict__ W,
                                              float* __restrict__ Y,
                                              const float* __restrict__ rowscale) {
    __shared__ float Ws[32][128];
    __shared__ float Xs[64][33];
    int tid  = threadIdx.x;
    int colg = tid & 7;       // 0..7
    int rowg = tid >> 3;      // 0..31
    int row0 = blockIdx.x * 64;

    unsigned long long acc2[2][8];
#pragma unroll
    for (int r = 0; r < 2; r++)
#pragma unroll
        for (int j = 0; j < 8; j++) acc2[r][j] = 0ull;

    for (int k0 = 0; k0 < 128; k0 += 32) {
#pragma unroll
        for (int i = 0; i < 16; i++) {
            int idx = tid + i * 256;
            int r = idx >> 7, c = idx & 127;
            Ws[r][c] = W[(k0 + r) * 128 + c];
        }
#pragma unroll
        for (int i = 0; i < 8; i++) {
            int idx = tid + i * 256;
            int r = idx >> 5, c = idx & 31;
            int gr = row0 + r;
            Xs[r][c] = (gr < NN) ? X[gr * 128 + k0 + c] : 0.f;
        }
        __syncthreads();
#pragma unroll
        for (int kk = 0; kk < 32; kk++) {
            unsigned long long w[8];
#pragma unroll
            for (int j = 0; j < 4; j++) {
                float4 w4 = *(const float4*)&Ws[kk][colg * 4 + 32 * j];
                asm("mov.b64 %0,{%1,%2};" : "=l"(w[2 * j])     : "f"(w4.x), "f"(w4.y));
                asm("mov.b64 %0,{%1,%2};" : "=l"(w[2 * j + 1]) : "f"(w4.z), "f"(w4.w));
            }
#pragma unroll
            for (int r = 0; r < 2; r++) {
                float xv = Xs[rowg * 2 + r][kk];
                unsigned long long xv2;
                asm("mov.b64 %0,{%1,%1};" : "=l"(xv2) : "f"(xv));
#pragma unroll
                for (int j = 0; j < 8; j++)
                    asm("fma.rn.f32x2 %0, %1, %2, %0;" : "+l"(acc2[r][j]) : "l"(xv2), "l"(w[j]));
            }
        }
        __syncthreads();
    }
#pragma unroll
    for (int r = 0; r < 2; r++) {
        int gr = row0 + rowg * 2 + r;
        if (gr >= NN) continue;
        float rs = rowscale ? rowscale[gr] : 1.f;
#pragma unroll
        for (int j = 0; j < 4; j++) {
            float a, b, c, d;
            asm("mov.b64 {%0,%1},%2;" : "=f"(a), "=f"(b) : "l"(acc2[r][2 * j]));
            asm("mov.b64 {%0,%1},%2;" : "=f"(c), "=f"(d) : "l"(acc2[r][2 * j + 1]));
            *(float4*)&Y[gr * 128 + colg * 4 + 32 * j] =
                make_float4(a * rs, b * rs, c * rs, d * rs);
        }
    }
}

// ---------------- GAT attention logits per node ----------------
__global__ void k_attdot(const float* __restrict__ att_s, const float* __restrict__ att_d) {
    int n = blockIdx.x * 8 + (threadIdx.x >> 5);
    if (n >= NN) return;
    int lane = threadIdx.x & 31;
    float4 h4 = ((const float4*)g_bufA)[n * 32 + lane];
    float4 s4 = ((const float4*)att_s)[lane];
    float4 d4 = ((const float4*)att_d)[lane];
    float ps = h4.x * s4.x + h4.y * s4.y + h4.z * s4.z + h4.w * s4.w;
    float pd = h4.x * d4.x + h4.y * d4.y + h4.z * d4.z + h4.w * d4.w;
#pragma unroll
    for (int o = 1; o < 8; o <<= 1) {
        ps += __shfl_xor_sync(0xffffffffu, ps, o);
        pd += __shfl_xor_sync(0xffffffffu, pd, o);
    }
    if ((lane & 7) == 0) {
        g_as[n * 4 + (lane >> 3)] = ps;
        g_ad[n * 4 + (lane >> 3)] = pd;
    }
}

// ---------------- GAT aggregation: warp per dst node ----------------
__global__ void k_gat(const float* __restrict__ xw, const float* __restrict__ gat_b,
                      float* __restrict__ out) {
    int n = blockIdx.x * 8 + (threadIdx.x >> 5);
    if (n >= NN) return;
    int lane = threadIdx.x & 31;
    int start = g_rowptr[n], end = g_rowptr[n + 1];
    float4 ad4 = ((const float4*)g_ad)[n];

    // pass 1: exp per edge per head (cached), accumulate per-head sums
    float s0 = 0.f, s1 = 0.f, s2 = 0.f, s3 = 0.f;
    for (int e = start + lane; e < end; e += 32) {
        int s = g_colsrc[e];
        float4 a4 = ((const float4*)g_as)[s];
        float e0 = __expf(lreluf(a4.x + ad4.x));
        float e1 = __expf(lreluf(a4.y + ad4.y));
        float e2 = __expf(lreluf(a4.z + ad4.z));
        float e3 = __expf(lreluf(a4.w + ad4.w));
        ((float4*)g_alpha)[e] = make_float4(e0, e1, e2, e3);
        s0 += e0; s1 += e1; s2 += e2; s3 += e3;
    }
#pragma unroll
    for (int o = 16; o; o >>= 1) {
        s0 += __shfl_xor_sync(0xffffffffu, s0, o);
        s1 += __shfl_xor_sync(0xffffffffu, s1, o);
        s2 += __shfl_xor_sync(0xffffffffu, s2, o);
        s3 += __shfl_xor_sync(0xffffffffu, s3, o);
    }
    int myh = lane >> 3;
    float inv_my = 1.f / (myh == 0 ? s0 : myh == 1 ? s1 : myh == 2 ? s2 : s3);

    // pass 2: weighted gather, unroll-4 for memory-level parallelism
    float4 acc = make_float4(0.f, 0.f, 0.f, 0.f);
    int e = start;
    for (; e + 4 <= end; e += 4) {
        int i0 = g_colsrc[e], i1 = g_colsrc[e + 1], i2 = g_colsrc[e + 2], i3 = g_colsrc[e + 3];
        float4 al0 = ((const float4*)g_alpha)[e];
        float4 al1 = ((const float4*)g_alpha)[e + 1];
        float4 al2 = ((const float4*)g_alpha)[e + 2];
        float4 al3 = ((const float4*)g_alpha)[e + 3];
        float4 x0 = ((const float4*)xw)[i0 * 32 + lane];
        float4 x1 = ((const float4*)xw)[i1 * 32 + lane];
        float4 x2 = ((const float4*)xw)[i2 * 32 + lane];
        float4 x3 = ((const float4*)xw)[i3 * 32 + lane];
        float a0 = (myh == 0 ? al0.x : myh == 1 ? al0.y : myh == 2 ? al0.z : al0.w) * inv_my;
        float a1 = (myh == 0 ? al1.x : myh == 1 ? al1.y : myh == 2 ? al1.z : al1.w) * inv_my;
        float a2 = (myh == 0 ? al2.x : myh == 1 ? al2.y : myh == 2 ? al2.z : al2.w) * inv_my;
        float a3 = (myh == 0 ? al3.x : myh == 1 ? al3.y : myh == 2 ? al3.z : al3.w) * inv_my;
        acc.x += a0 * x0.x + a1 * x1.x + a2 * x2.x + a3 * x3.x;
        acc.y += a0 * x0.y + a1 * x1.y + a2 * x2.y + a3 * x3.y;
        acc.z += a0 * x0.z + a1 * x1.z + a2 * x2.z + a3 * x3.z;
        acc.w += a0 * x0.w + a1 * x1.w + a2 * x2.w + a3 * x3.w;
    }
    for (; e < end; e++) {
        int s = g_colsrc[e];
        float4 al4 = ((const float4*)g_alpha)[e];
        float al = (myh == 0 ? al4.x : myh == 1 ? al4.y : myh == 2 ? al4.z : al4.w) * inv_my;
        float4 x4 = ((const float4*)xw)[s * 32 + lane];
        acc.x += al * x4.x; acc.y += al * x4.y; acc.z += al * x4.z; acc.w += al * x4.w;
    }
    float4 b4 = ((const float4*)gat_b)[lane];
    float4 o4;
    o4.x = eluf(acc.x + b4.x);
    o4.y = eluf(acc.y + b4.y);
    o4.z = eluf(acc.z + b4.z);
    o4.w = eluf(acc.w + b4.w);
    ((float4*)out)[n * 32 + lane] = o4;
}

// ---------------- GCN aggregation + BN + ELU (+residual): warp per dst ----------------
// xw rows are PRE-SCALED by dinv[src] in the GEMM epilogue.
__global__ void k_gcn(const float* __restrict__ xw, const float* __restrict__ resid,
                      float* __restrict__ out, const float* __restrict__ bias,
                      const float* __restrict__ bng, const float* __restrict__ bnb,
                      const float* __restrict__ bnm, const float* __restrict__ bnv) {
    int n = blockIdx.x * 8 + (threadIdx.x >> 5);
    if (n >= NN) return;
    int lane = threadIdx.x & 31;
    int start = g_rowptr[n], end = g_rowptr[n + 1];
    float di = g_dinv[n];
    float4 acc = make_float4(0.f, 0.f, 0.f, 0.f);
    int e = start;
    for (; e + 4 <= end; e += 4) {
        int i0 = g_colsrc[e], i1 = g_colsrc[e + 1], i2 = g_colsrc[e + 2], i3 = g_colsrc[e + 3];
        float4 x0 = ((const float4*)xw)[i0 * 32 + lane];
        float4 x1 = ((const float4*)xw)[i1 * 32 + lane];
        float4 x2 = ((const float4*)xw)[i2 * 32 + lane];
        float4 x3 = ((const float4*)xw)[i3 * 32 + lane];
        acc.x += (x0.x + x1.x) + (x2.x + x3.x);
        acc.y += (x0.y + x1.y) + (x2.y + x3.y);
        acc.z += (x0.z + x1.z) + (x2.z + x3.z);
        acc.w += (x0.w + x1.w) + (x2.w + x3.w);
    }
    for (; e < end; e++) {
        int s = g_colsrc[e];
        float4 x4 = ((const float4*)xw)[s * 32 + lane];
        acc.x += x4.x; acc.y += x4.y; acc.z += x4.z; acc.w += x4.w;
    }
    float4 b4 = ((const float4*)bias)[lane];
    float4 g4 = ((const float4*)bng)[lane];
    float4 bb4 = ((const float4*)bnb)[lane];
    float4 m4 = ((const float4*)bnm)[lane];
    float4 v4 = ((const float4*)bnv)[lane];
    float4 r4 = make_float4(0.f, 0.f, 0.f, 0.f);
    if (resid) r4 = ((const float4*)resid)[n * 32 + lane];
    float4 o4;
    {
        float y = acc.x * di + b4.x;
        float sc = g4.x * rsqrtf(v4.x + BN_EPS);
        o4.x = eluf((y - m4.x) * sc + bb4.x) + r4.x;
    }
    {
        float y = acc.y * di + b4.y;
        float sc = g4.y * rsqrtf(v4.y + BN_EPS);
        o4.y = eluf((y - m4.y) * sc + bb4.y) + r4.y;
    }
    {
        float y = acc.z * di + b4.z;
        float sc = g4.z * rsqrtf(v4.z + BN_EPS);
        o4.z = eluf((y - m4.z) * sc + bb4.z) + r4.z;
    }
    {
        float y = acc.w * di + b4.w;
        float sc = g4.w * rsqrtf(v4.w + BN_EPS);
        o4.w = eluf((y - m4.w) * sc + bb4.w) + r4.w;
    }
    ((float4*)out)[n * 32 + lane] = o4;
}

// ---------------- global mean pool accumulate ----------------
__global__ void k_pool(const float* __restrict__ h, const void* __restrict__ batch) {
    int n = blockIdx.x * 8 + (threadIdx.x >> 5);
    if (n >= NN) return;
    int lane = threadIdx.x & 31;
    int g = ld_idx(batch, n);
    float4 x4 = ((const float4*)h)[n * 32 + lane];
    float* p = &g_pool[g * 128 + lane * 4];
    atomicAdd(p + 0, x4.x);
    atomicAdd(p + 1, x4.y);
    atomicAdd(p + 2, x4.z);
    atomicAdd(p + 3, x4.w);
    if (lane == 0) atomicAdd(&g_pcnt[g], 1);
}

// ---------------- MLP head: one block per graph ----------------
__global__ void k_mlp(const float* __restrict__ p1w, const float* __restrict__ p1b,
                      const float* __restrict__ p2w, const float* __restrict__ p2b,
                      const float* __restrict__ cw,  const float* __restrict__ cb,
                      float* __restrict__ out, int out_size) {
    __shared__ float gs[128], e1[128], e2[64];
    int b = blockIdx.x, t = threadIdx.x;
    float cnt = fmaxf((float)g_pcnt[b], 1.f);
    gs[t] = g_pool[b * 128 + t] / cnt;
    __syncthreads();
    float a = p1b[t];
#pragma unroll 8
    for (int k = 0; k < 128; k++) a += gs[k] * p1w[k * 128 + t];
    e1[t] = eluf(a);
    __syncthreads();
    if (t < 64) {
        float a2 = p2b[t];
#pragma unroll 8
        for (int k = 0; k < 128; k++) a2 += e1[k] * p2w[k * 64 + t];
        e2[t] = a2;
        if (out_size >= 1024 * 3 + 1024 * 64) out[1024 * 3 + b * 64 + t] = a2;
    }
    __syncthreads();
    if (t < 3) {
        float a3 = cb[t];
#pragma unroll
        for (int k = 0; k < 64; k++) a3 += e2[k] * cw[k * 3 + t];
        out[b * 3 + t] = a3;
    }
}

// ---------------- launch ----------------
extern "C" void kernel_launch(void* const* d_in, const int* in_sizes, int n_in,
                              void* d_out, int out_size) {
    const float* x      = (const float*)d_in[0];
    const void*  ei     = d_in[1];               // int32 or int64, detected at runtime
    const void*  batch  = d_in[3];
    const float* gat_w  = (const float*)d_in[4];
    const float* att_s  = (const float*)d_in[5];
    const float* att_d  = (const float*)d_in[6];
    const float* gat_b  = (const float*)d_in[7];
    const float* gcn1_w = (const float*)d_in[8];
    const float* gcn1_b = (const float*)d_in[9];
    const float* bn1_g  = (const float*)d_in[10];
    const float* bn1_b  = (const float*)d_in[11];
    const float* bn1_m  = (const float*)d_in[12];
    const float* bn1_v  = (const float*)d_in[13];
    const float* gcn2_w = (const float*)d_in[14];
    const float* gcn2_b = (const float*)d_in[15];
    const float* bn2_g  = (const float*)d_in[16];
    const float* bn2_b  = (const float*)d_in[17];
    const float* bn2_m  = (const float*)d_in[18];
    const float* bn2_v  = (const float*)d_in[19];
    const float* gcn3_w = (const float*)d_in[20];
    const float* gcn3_b = (const float*)d_in[21];
    const float* bn3_g  = (const float*)d_in[22];
    const float* bn3_b  = (const float*)d_in[23];
    const float* bn3_m  = (const float*)d_in[24];
    const float* bn3_v  = (const float*)d_in[25];
    const float* p1_w   = (const float*)d_in[26];
    const float* p1_b   = (const float*)d_in[27];
    const float* p2_w   = (const float*)d_in[28];
    const float* p2_b   = (const float*)d_in[29];
    const float* cls_w  = (const float*)d_in[30];
    const float* cls_b  = (const float*)d_in[31];
    float* out = (float*)d_out;

    float *pA, *pB, *pC, *pDinv;
    cudaGetSymbolAddress((void**)&pA, g_bufA);
    cudaGetSymbolAddress((void**)&pB, g_bufB);
    cudaGetSymbolAddress((void**)&pC, g_bufC);
    cudaGetSymbolAddress((void**)&pDinv, g_dinv);

    const int EB = (NE2 + 255) / 256;
    const int NB = (NN + 255) / 256;
    const int WB = NN / 8;             // warp-per-node blocks (256 thr = 8 warps)
    const int GB = (NN + 63) / 64;     // gemm blocks

    k_detect<<<1, 32>>>((const int*)ei);
    k_zero<<<512, 256>>>();
    k_count<<<EB, 256>>>(ei);
    k_scan1<<<98, 1024>>>();
    k_scan2<<<1, 32>>>(98);
    k_scan3<<<NB, 256>>>();
    k_fill<<<EB, 256>>>(ei);

    // GAT
    k_gemm<<<GB, 256>>>(x, gat_w, pA, nullptr);
    k_attdot<<<WB, 256>>>(att_s, att_d);
    k_gat<<<WB, 256>>>(pA, gat_b, pB);
    // GCN1 (+res B) — xw rows pre-scaled by dinv
    k_gemm<<<GB, 256>>>(pB, gcn1_w, pA, pDinv);
    k_gcn<<<WB, 256>>>(pA, pB, pC, gcn1_b, bn1_g, bn1_b, bn1_m, bn1_v);
    // GCN2 (+res C)
    k_gemm<<<GB, 256>>>(pC, gcn2_w, pA, pDinv);
    k_gcn<<<WB, 256>>>(pA, pC, pB, gcn2_b, bn2_g, bn2_b, bn2_m, bn2_v);
    // GCN3 (no res)
    k_gemm<<<GB, 256>>>(pB, gcn3_w, pA, pDinv);
    k_gcn<<<WB, 256>>>(pA, (const float*)nullptr, pC, gcn3_b, bn3_g, bn3_b, bn3_m, bn3_v);

    // pool + head
    k_pool<<<WB, 256>>>(pC, batch);
    k_mlp<<<NG, 128>>>(p1_w, p1_b, p2_w, p2_b, cls_w, cls_b, out, out_size);
}

// round 7
// speedup vs baseline: 1.1686x; 1.0309x over previous
#include <cuda_runtime.h>
#include <cuda_fp16.h>
#include <math.h>

#define NN   100000
#define NE   1600000
#define NE2  1700000      // NE + NN self loops
#define HIDC 128
#define NG   1024
#define BN_EPS 1e-5f

// ---------------- scratch (static __device__, no allocation) ----------------
__device__ __half g_msg[NN * HIDC];   // fp16 message buffer (gathered per edge)
__device__ float g_bufB[NN * HIDC];   // h ping (fp32)
__device__ float g_bufC[NN * HIDC];   // h pong (fp32)
__device__ int   g_cnt[NN];
__device__ int   g_scan[NN];
__device__ int   g_rowptr[NN + 1];
__device__ int   g_cursor[NN];
__device__ int   g_colsrc[NE2];
__device__ float g_dinv[NN];
__device__ float g_as[NN * 4];
__device__ float g_ad[NN * 4];
__device__ float g_alpha[NE2 * 4];    // cached unnormalized exp per edge per head
__device__ int   g_bsum[128];
__device__ float g_pool[NG * HIDC];
__device__ int   g_pcnt[NG];
__device__ int   g_idx64;             // 1 if index arrays are int64, 0 if int32

__device__ __forceinline__ float eluf(float x)  { return x > 0.f ? x : (__expf(x) - 1.f); }
__device__ __forceinline__ float lreluf(float x){ return x > 0.f ? x : 0.2f * x; }

__device__ __forceinline__ int ld_idx(const void* p, int i) {
    if (g_idx64) return (int)((const long long*)p)[i];
    return ((const int*)p)[i];
}

// unpack uint2 (4 halves) to 4 floats
__device__ __forceinline__ float4 up4(uint2 u) {
    float2 lo = __half22float2(*(const half2*)&u.x);
    float2 hi = __half22float2(*(const half2*)&u.y);
    return make_float4(lo.x, lo.y, hi.x, hi.y);
}

// ---------------- dtype detection ----------------
__global__ void k_detect(const int* __restrict__ ei_words) {
    if (threadIdx.x == 0) {
        int is64 = 1;
        for (int i = 1; i < 512; i += 2)
            if (ei_words[i] != 0) { is64 = 0; break; }
        g_idx64 = is64;
    }
}

// ---------------- init / CSR build ----------------
__global__ void k_zero() {
    int i = blockIdx.x * blockDim.x + threadIdx.x;
    if (i < NN) g_cnt[i] = 0;
    if (i < NG * HIDC) g_pool[i] = 0.f;
    if (i < NG) g_pcnt[i] = 0;
}

__global__ void k_count(const void* __restrict__ ei) {
    int i = blockIdx.x * blockDim.x + threadIdx.x;
    if (i >= NE2) return;
    int dst = (i < NE) ? ld_idx(ei, NE + i) : (i - NE);
    atomicAdd(&g_cnt[dst], 1);
}

__global__ void k_scan1() {
    __shared__ int sm[1024];
    int t = threadIdx.x;
    int i = blockIdx.x * 1024 + t;
    int v = (i < NN) ? g_cnt[i] : 0;
    sm[t] = v;
    __syncthreads();
    for (int o = 1; o < 1024; o <<= 1) {
        int a = (t >= o) ? sm[t - o] : 0;
        __syncthreads();
        sm[t] += a;
        __syncthreads();
    }
    if (i < NN) g_scan[i] = sm[t];
    if (t == 1023) g_bsum[blockIdx.x] = sm[1023];
}

__global__ void k_scan2(int nb) {
    if (threadIdx.x == 0) {
        int run = 0;
        for (int b = 0; b < nb; b++) { int t = g_bsum[b]; g_bsum[b] = run; run += t; }
    }
}

__global__ void k_scan3() {
    int i = blockIdx.x * blockDim.x + threadIdx.x;
    if (i >= NN) return;
    int ex = g_scan[i] - g_cnt[i] + g_bsum[i >> 10];
    g_rowptr[i] = ex;
    g_cursor[i] = ex;
    g_dinv[i]   = rsqrtf((float)g_cnt[i]);
    if (i == 0) g_rowptr[NN] = NE2;
}

__global__ void k_fill(const void* __restrict__ ei) {
    int i = blockIdx.x * blockDim.x + threadIdx.x;
    if (i >= NE2) return;
    int src, dst;
    if (i < NE) { src = ld_idx(ei, i); dst = ld_idx(ei, NE + i); }
    else        { src = dst = i - NE; }
    int slot = atomicAdd(&g_cursor[dst], 1);
    g_colsrc[slot] = src;
}

// ---------------- fp32 GEMM (FFMA2), out = X[NN,128] @ W[128,128]
// Output: fp16 message buffer Yh, optionally row-scaled by rowscale[r].
__global__ void __launch_bounds__(256) k_gemm(const float* __restrict__ X,
                                              const float* __restrict__ W,
                                              __half* __restrict__ Yh,
                                              const float* __restrict__ rowscale) {
    __shared__ float Ws[32][128];
    __shared__ float Xs[64][33];
    int tid  = threadIdx.x;
    int colg = tid & 7;       // 0..7
    int rowg = tid >> 3;      // 0..31
    int row0 = blockIdx.x * 64;

    unsigned long long acc2[2][8];
#pragma unroll
    for (int r = 0; r < 2; r++)
#pragma unroll
        for (int j = 0; j < 8; j++) acc2[r][j] = 0ull;

    for (int k0 = 0; k0 < 128; k0 += 32) {
#pragma unroll
        for (int i = 0; i < 16; i++) {
            int idx = tid + i * 256;
            int r = idx >> 7, c = idx & 127;
            Ws[r][c] = W[(k0 + r) * 128 + c];
        }
#pragma unroll
        for (int i = 0; i < 8; i++) {
            int idx = tid + i * 256;
            int r = idx >> 5, c = idx & 31;
            int gr = row0 + r;
            Xs[r][c] = (gr < NN) ? X[gr * 128 + k0 + c] : 0.f;
        }
        __syncthreads();
#pragma unroll
        for (int kk = 0; kk < 32; kk++) {
            unsigned long long w[8];
#pragma unroll
            for (int j = 0; j < 4; j++) {
                float4 w4 = *(const float4*)&Ws[kk][colg * 4 + 32 * j];
                asm("mov.b64 %0,{%1,%2};" : "=l"(w[2 * j])     : "f"(w4.x), "f"(w4.y));
                asm("mov.b64 %0,{%1,%2};" : "=l"(w[2 * j + 1]) : "f"(w4.z), "f"(w4.w));
            }
#pragma unroll
            for (int r = 0; r < 2; r++) {
                float xv = Xs[rowg * 2 + r][kk];
                unsigned long long xv2;
                asm("mov.b64 %0,{%1,%1};" : "=l"(xv2) : "f"(xv));
#pragma unroll
                for (int j = 0; j < 8; j++)
                    asm("fma.rn.f32x2 %0, %1, %2, %0;" : "+l"(acc2[r][j]) : "l"(xv2), "l"(w[j]));
            }
        }
        __syncthreads();
    }
#pragma unroll
    for (int r = 0; r < 2; r++) {
        int gr = row0 + rowg * 2 + r;
        if (gr >= NN) continue;
        float rs = rowscale ? rowscale[gr] : 1.f;
#pragma unroll
        for (int j = 0; j < 4; j++) {
            float a, b, c, d;
            asm("mov.b64 {%0,%1},%2;" : "=f"(a), "=f"(b) : "l"(acc2[r][2 * j]));
            asm("mov.b64 {%0,%1},%2;" : "=f"(c), "=f"(d) : "l"(acc2[r][2 * j + 1]));
            half2 h01 = __floats2half2_rn(a * rs, b * rs);
            half2 h23 = __floats2half2_rn(c * rs, d * rs);
            uint2 u;
            u.x = *(unsigned*)&h01;
            u.y = *(unsigned*)&h23;
            // uint2 index: row*32 + colg + 8*j  (4 halves per uint2)
            ((uint2*)Yh)[gr * 32 + colg + 8 * j] = u;
        }
    }
}

// ---------------- GAT attention logits per node (reads fp16 msg) ----------------
__global__ void k_attdot(const float* __restrict__ att_s, const float* __restrict__ att_d) {
    int n = blockIdx.x * 8 + (threadIdx.x >> 5);
    if (n >= NN) return;
    int lane = threadIdx.x & 31;
    float4 h4 = up4(((const uint2*)g_msg)[n * 32 + lane]);
    float4 s4 = ((const float4*)att_s)[lane];
    float4 d4 = ((const float4*)att_d)[lane];
    float ps = h4.x * s4.x + h4.y * s4.y + h4.z * s4.z + h4.w * s4.w;
    float pd = h4.x * d4.x + h4.y * d4.y + h4.z * d4.z + h4.w * d4.w;
#pragma unroll
    for (int o = 1; o < 8; o <<= 1) {
        ps += __shfl_xor_sync(0xffffffffu, ps, o);
        pd += __shfl_xor_sync(0xffffffffu, pd, o);
    }
    if ((lane & 7) == 0) {
        g_as[n * 4 + (lane >> 3)] = ps;
        g_ad[n * 4 + (lane >> 3)] = pd;
    }
}

// ---------------- GAT aggregation: warp per dst node ----------------
__global__ void k_gat(const float* __restrict__ gat_b, float* __restrict__ out) {
    int n = blockIdx.x * 8 + (threadIdx.x >> 5);
    if (n >= NN) return;
    int lane = threadIdx.x & 31;
    int start = g_rowptr[n], end = g_rowptr[n + 1];
    float4 ad4 = ((const float4*)g_ad)[n];
    const uint2* m2 = (const uint2*)g_msg;

    // pass 1: exp per edge per head (cached), accumulate per-head sums
    float s0 = 0.f, s1 = 0.f, s2 = 0.f, s3 = 0.f;
    for (int e = start + lane; e < end; e += 32) {
        int s = g_colsrc[e];
        float4 a4 = ((const float4*)g_as)[s];
        float e0 = __expf(lreluf(a4.x + ad4.x));
        float e1 = __expf(lreluf(a4.y + ad4.y));
        float e2 = __expf(lreluf(a4.z + ad4.z));
        float e3 = __expf(lreluf(a4.w + ad4.w));
        ((float4*)g_alpha)[e] = make_float4(e0, e1, e2, e3);
        s0 += e0; s1 += e1; s2 += e2; s3 += e3;
    }
#pragma unroll
    for (int o = 16; o; o >>= 1) {
        s0 += __shfl_xor_sync(0xffffffffu, s0, o);
        s1 += __shfl_xor_sync(0xffffffffu, s1, o);
        s2 += __shfl_xor_sync(0xffffffffu, s2, o);
        s3 += __shfl_xor_sync(0xffffffffu, s3, o);
    }
    int myh = lane >> 3;
    float inv_my = 1.f / (myh == 0 ? s0 : myh == 1 ? s1 : myh == 2 ? s2 : s3);

    // pass 2: weighted gather (fp16 msg), unroll-4 for MLP
    float4 acc = make_float4(0.f, 0.f, 0.f, 0.f);
    int e = start;
    for (; e + 4 <= end; e += 4) {
        int i0 = g_colsrc[e], i1 = g_colsrc[e + 1], i2 = g_colsrc[e + 2], i3 = g_colsrc[e + 3];
        float4 al0 = ((const float4*)g_alpha)[e];
        float4 al1 = ((const float4*)g_alpha)[e + 1];
        float4 al2 = ((const float4*)g_alpha)[e + 2];
        float4 al3 = ((const float4*)g_alpha)[e + 3];
        float4 x0 = up4(m2[i0 * 32 + lane]);
        float4 x1 = up4(m2[i1 * 32 + lane]);
        float4 x2 = up4(m2[i2 * 32 + lane]);
        float4 x3 = up4(m2[i3 * 32 + lane]);
        float a0 = (myh == 0 ? al0.x : myh == 1 ? al0.y : myh == 2 ? al0.z : al0.w) * inv_my;
        float a1 = (myh == 0 ? al1.x : myh == 1 ? al1.y : myh == 2 ? al1.z : al1.w) * inv_my;
        float a2 = (myh == 0 ? al2.x : myh == 1 ? al2.y : myh == 2 ? al2.z : al2.w) * inv_my;
        float a3 = (myh == 0 ? al3.x : myh == 1 ? al3.y : myh == 2 ? al3.z : al3.w) * inv_my;
        acc.x += a0 * x0.x + a1 * x1.x + a2 * x2.x + a3 * x3.x;
        acc.y += a0 * x0.y + a1 * x1.y + a2 * x2.y + a3 * x3.y;
        acc.z += a0 * x0.z + a1 * x1.z + a2 * x2.z + a3 * x3.z;
        acc.w += a0 * x0.w + a1 * x1.w + a2 * x2.w + a3 * x3.w;
    }
    for (; e < end; e++) {
        int s = g_colsrc[e];
        float4 al4 = ((const float4*)g_alpha)[e];
        float al = (myh == 0 ? al4.x : myh == 1 ? al4.y : myh == 2 ? al4.z : al4.w) * inv_my;
        float4 x4 = up4(m2[s * 32 + lane]);
        acc.x += al * x4.x; acc.y += al * x4.y; acc.z += al * x4.z; acc.w += al * x4.w;
    }
    float4 b4 = ((const float4*)gat_b)[lane];
    float4 o4;
    o4.x = eluf(acc.x + b4.x);
    o4.y = eluf(acc.y + b4.y);
    o4.z = eluf(acc.z + b4.z);
    o4.w = eluf(acc.w + b4.w);
    ((float4*)out)[n * 32 + lane] = o4;
}

// ---------------- GCN aggregation + BN + ELU (+residual): warp per dst ----------------
// messages in g_msg are PRE-SCALED by dinv[src] (GEMM epilogue).
__global__ void k_gcn(const float* __restrict__ resid,
                      float* __restrict__ out, const float* __restrict__ bias,
                      const float* __restrict__ bng, const float* __restrict__ bnb,
                      const float* __restrict__ bnm, const float* __restrict__ bnv) {
    int n = blockIdx.x * 8 + (threadIdx.x >> 5);
    if (n >= NN) return;
    int lane = threadIdx.x & 31;
    int start = g_rowptr[n], end = g_rowptr[n + 1];
    float di = g_dinv[n];
    const uint2* m2 = (const uint2*)g_msg;
    float4 acc = make_float4(0.f, 0.f, 0.f, 0.f);
    int e = start;
    for (; e + 4 <= end; e += 4) {
        int i0 = g_colsrc[e], i1 = g_colsrc[e + 1], i2 = g_colsrc[e + 2], i3 = g_colsrc[e + 3];
        float4 x0 = up4(m2[i0 * 32 + lane]);
        float4 x1 = up4(m2[i1 * 32 + lane]);
        float4 x2 = up4(m2[i2 * 32 + lane]);
        float4 x3 = up4(m2[i3 * 32 + lane]);
        acc.x += (x0.x + x1.x) + (x2.x + x3.x);
        acc.y += (x0.y + x1.y) + (x2.y + x3.y);
        acc.z += (x0.z + x1.z) + (x2.z + x3.z);
        acc.w += (x0.w + x1.w) + (x2.w + x3.w);
    }
    for (; e < end; e++) {
        int s = g_colsrc[e];
        float4 x4 = up4(m2[s * 32 + lane]);
        acc.x += x4.x; acc.y += x4.y; acc.z += x4.z; acc.w += x4.w;
    }
    float4 b4 = ((const float4*)bias)[lane];
    float4 g4 = ((const float4*)bng)[lane];
    float4 bb4 = ((const float4*)bnb)[lane];
    float4 m4 = ((const float4*)bnm)[lane];
    float4 v4 = ((const float4*)bnv)[lane];
    float4 r4 = make_float4(0.f, 0.f, 0.f, 0.f);
    if (resid) r4 = ((const float4*)resid)[n * 32 + lane];
    float4 o4;
    {
        float y = acc.x * di + b4.x;
        float sc = g4.x * rsqrtf(v4.x + BN_EPS);
        o4.x = eluf((y - m4.x) * sc + bb4.x) + r4.x;
    }
    {
        float y = acc.y * di + b4.y;
        float sc = g4.y * rsqrtf(v4.y + BN_EPS);
        o4.y = eluf((y - m4.y) * sc + bb4.y) + r4.y;
    }
    {
        float y = acc.z * di + b4.z;
        float sc = g4.z * rsqrtf(v4.z + BN_EPS);
        o4.z = eluf((y - m4.z) * sc + bb4.z) + r4.z;
    }
    {
        float y = acc.w * di + b4.w;
        float sc = g4.w * rsqrtf(v4.w + BN_EPS);
        o4.w = eluf((y - m4.w) * sc + bb4.w) + r4.w;
    }
    ((float4*)out)[n * 32 + lane] = o4;
}

// ---------------- global mean pool accumulate ----------------
__global__ void k_pool(const float* __restrict__ h, const void* __restrict__ batch) {
    int n = blockIdx.x * 8 + (threadIdx.x >> 5);
    if (n >= NN) return;
    int lane = threadIdx.x & 31;
    int g = ld_idx(batch, n);
    float4 x4 = ((const float4*)h)[n * 32 + lane];
    float* p = &g_pool[g * 128 + lane * 4];
    atomicAdd(p + 0, x4.x);
    atomicAdd(p + 1, x4.y);
    atomicAdd(p + 2, x4.z);
    atomicAdd(p + 3, x4.w);
    if (lane == 0) atomicAdd(&g_pcnt[g], 1);
}

// ---------------- MLP head: one block per graph ----------------
__global__ void k_mlp(const float* __restrict__ p1w, const float* __restrict__ p1b,
                      const float* __restrict__ p2w, const float* __restrict__ p2b,
                      const float* __restrict__ cw,  const float* __restrict__ cb,
                      float* __restrict__ out, int out_size) {
    __shared__ float gs[128], e1[128], e2[64];
    int b = blockIdx.x, t = threadIdx.x;
    float cnt = fmaxf((float)g_pcnt[b], 1.f);
    gs[t] = g_pool[b * 128 + t] / cnt;
    __syncthreads();
    float a = p1b[t];
#pragma unroll 8
    for (int k = 0; k < 128; k++) a += gs[k] * p1w[k * 128 + t];
    e1[t] = eluf(a);
    __syncthreads();
    if (t < 64) {
        float a2 = p2b[t];
#pragma unroll 8
        for (int k = 0; k < 128; k++) a2 += e1[k] * p2w[k * 64 + t];
        e2[t] = a2;
        if (out_size >= 1024 * 3 + 1024 * 64) out[1024 * 3 + b * 64 + t] = a2;
    }
    __syncthreads();
    if (t < 3) {
        float a3 = cb[t];
#pragma unroll
        for (int k = 0; k < 64; k++) a3 += e2[k] * cw[k * 3 + t];
        out[b * 3 + t] = a3;
    }
}

// ---------------- launch ----------------
extern "C" void kernel_launch(void* const* d_in, const int* in_sizes, int n_in,
                              void* d_out, int out_size) {
    const float* x      = (const float*)d_in[0];
    const void*  ei     = d_in[1];               // int32 or int64, detected at runtime
    const void*  batch  = d_in[3];
    const float* gat_w  = (const float*)d_in[4];
    const float* att_s  = (const float*)d_in[5];
    const float* att_d  = (const float*)d_in[6];
    const float* gat_b  = (const float*)d_in[7];
    const float* gcn1_w = (const float*)d_in[8];
    const float* gcn1_b = (const float*)d_in[9];
    const float* bn1_g  = (const float*)d_in[10];
    const float* bn1_b  = (const float*)d_in[11];
    const float* bn1_m  = (const float*)d_in[12];
    const float* bn1_v  = (const float*)d_in[13];
    const float* gcn2_w = (const float*)d_in[14];
    const float* gcn2_b = (const float*)d_in[15];
    const float* bn2_g  = (const float*)d_in[16];
    const float* bn2_b  = (const float*)d_in[17];
    const float* bn2_m  = (const float*)d_in[18];
    const float* bn2_v  = (const float*)d_in[19];
    const float* gcn3_w = (const float*)d_in[20];
    const float* gcn3_b = (const float*)d_in[21];
    const float* bn3_g  = (const float*)d_in[22];
    const float* bn3_b  = (const float*)d_in[23];
    const float* bn3_m  = (const float*)d_in[24];
    const float* bn3_v  = (const float*)d_in[25];
    const float* p1_w   = (const float*)d_in[26];
    const float* p1_b   = (const float*)d_in[27];
    const float* p2_w   = (const float*)d_in[28];
    const float* p2_b   = (const float*)d_in[29];
    const float* cls_w  = (const float*)d_in[30];
    const float* cls_b  = (const float*)d_in[31];
    float* out = (float*)d_out;

    float *pB, *pC, *pDinv;
    __half* pMsg;
    cudaGetSymbolAddress((void**)&pB, g_bufB);
    cudaGetSymbolAddress((void**)&pC, g_bufC);
    cudaGetSymbolAddress((void**)&pDinv, g_dinv);
    cudaGetSymbolAddress((void**)&pMsg, g_msg);

    const int EB = (NE2 + 255) / 256;
    const int NB = (NN + 255) / 256;
    const int WB = NN / 8;             // warp-per-node blocks (256 thr = 8 warps)
    const int GB = (NN + 63) / 64;     // gemm blocks

    k_detect<<<1, 32>>>((const int*)ei);
    k_zero<<<512, 256>>>();
    k_count<<<EB, 256>>>(ei);
    k_scan1<<<98, 1024>>>();
    k_scan2<<<1, 32>>>(98);
    k_scan3<<<NB, 256>>>();
    k_fill<<<EB, 256>>>(ei);

    // GAT: msg = x @ gat_w (fp16)
    k_gemm<<<GB, 256>>>(x, gat_w, pMsg, nullptr);
    k_attdot<<<WB, 256>>>(att_s, att_d);
    k_gat<<<WB, 256>>>(gat_b, pB);
    // GCN1 (+res B): msg = dinv * (B @ gcn1_w) (fp16)
    k_gemm<<<GB, 256>>>(pB, gcn1_w, pMsg, pDinv);
    k_gcn<<<WB, 256>>>(pB, pC, gcn1_b, bn1_g, bn1_b, bn1_m, bn1_v);
    // GCN2 (+res C)
    k_gemm<<<GB, 256>>>(pC, gcn2_w, pMsg, pDinv);
    k_gcn<<<WB, 256>>>(pC, pB, gcn2_b, bn2_g, bn2_b, bn2_m, bn2_v);
    // GCN3 (no res)
    k_gemm<<<GB, 256>>>(pB, gcn3_w, pMsg, pDinv);
    k_gcn<<<WB, 256>>>((const float*)nullptr, pC, gcn3_b, bn3_g, bn3_b, bn3_m, bn3_v);

    // pool + head
    k_pool<<<WB, 256>>>(pC, batch);
    k_mlp<<<NG, 128>>>(p1_w, p1_b, p2_w, p2_b, cls_w, cls_b, out, out_size);
}